// round 1
// baseline (speedup 1.0000x reference)
#include <cuda_runtime.h>
#include <math.h>

#define B_ 32
#define C_ 128
#define N_ 307
#define TL 12
#define TH 13
#define TMAX 13
#define LAYERS 4
#define BN_EPS 1e-5f

// ---------------- scratch (static __device__, no allocations) ----------------
__device__ float g_G [2*4*B_*TMAX*N_];   // (ch,layer,b,s,n)
__device__ float g_H [2*4*B_*TMAX*C_];   // (ch,layer,b,s,c)
__device__ float g_GW[2*4*B_*TMAX*C_];   // (ch,layer,b,s,c)
__device__ float g_logits[2][2*B_*TMAX*TMAX]; // double buffered per layer parity
__device__ float g_avec[2*B_*TMAX];      // final A column per (ch,b)
__device__ unsigned g_bar_count;
__device__ unsigned g_bar_gen;

__device__ __forceinline__ int Gidx(int ch,int i,int b,int s,int n){
    return (((ch*4+i)*B_+b)*TMAX+s)*N_+n;
}
__device__ __forceinline__ int Hidx(int ch,int i,int b,int s,int c){
    return (((ch*4+i)*B_+b)*TMAX+s)*C_+c;
}

// grid barrier: grid is 64 blocks <= 148 SMs -> all co-resident.
__device__ __forceinline__ void grid_barrier(unsigned nb){
    __threadfence();
    __syncthreads();
    if (threadIdx.x == 0){
        unsigned gen = atomicAdd(&g_bar_gen, 0u);
        unsigned arrived = atomicAdd(&g_bar_count, 1u);
        if (arrived == nb - 1u){
            atomicExch(&g_bar_count, 0u);
            __threadfence();
            atomicAdd(&g_bar_gen, 1u);
        } else {
            while (atomicAdd(&g_bar_gen, 0u) == gen) { __nanosleep(64); }
        }
    }
    __syncthreads();
}

// ---------------- K1a: G[ch][i][b][s][n] = sum_c c1_i[c] * x0[b,c,n,s] ------
// block = (b, n-tile of 32) x channel; thread = (n_local, s); loop over all c.
__global__ void __launch_bounds__(416) k1a_kernel(
    const float* __restrict__ XL, const float* __restrict__ XH,
    const float* __restrict__ c1L, const float* __restrict__ c1H)
{
    int ch = blockIdx.y;
    int b  = blockIdx.x / 10;
    int nt = blockIdx.x % 10;
    int T  = ch ? TH : TL;
    const float* X  = ch ? XH : XL;
    const float* c1 = ch ? c1H : c1L;

    __shared__ float4 sc1[C_];
    int tid = threadIdx.x;
    if (tid < C_)
        sc1[tid] = make_float4(c1[tid], c1[C_+tid], c1[2*C_+tid], c1[3*C_+tid]);
    __syncthreads();

    if (tid >= 32*T) return;
    int s  = tid % T;
    int nl = tid / T;
    int n  = nt*32 + nl;
    if (n >= N_) return;

    float g0=0.f,g1=0.f,g2=0.f,g3=0.f;
    bool zero = (ch && s == 0);   // high channel left-pad: x0[...,0] == 0
    if (!zero){
        const float* base = X + ((size_t)b*C_*N_ + n)*TL + (ch ? s-1 : s);
        #pragma unroll 4
        for (int c = 0; c < C_; c++){
            float v = base[(size_t)c*N_*TL];
            float4 w = sc1[c];
            g0 = fmaf(w.x, v, g0);
            g1 = fmaf(w.y, v, g1);
            g2 = fmaf(w.z, v, g2);
            g3 = fmaf(w.w, v, g3);
        }
    }
    g_G[Gidx(ch,0,b,s,n)] = g0;
    g_G[Gidx(ch,1,b,s,n)] = g1;
    g_G[Gidx(ch,2,b,s,n)] = g2;
    g_G[Gidx(ch,3,b,s,n)] = g3;
}

// ---------------- K1b: H[ch][i][b][s][c] = sum_n c2_i[n] * x0[b,c,n,s] ------
// block = (b, c-tile of 32) x channel; smem-stage n-chunks for coalesced loads.
#define NCH 16
__global__ void __launch_bounds__(416) k1b_kernel(
    const float* __restrict__ XL, const float* __restrict__ XH,
    const float* __restrict__ c2L, const float* __restrict__ c2H)
{
    int ch = blockIdx.y;
    int b  = blockIdx.x / 4;
    int cb = blockIdx.x % 4;
    int T  = ch ? TH : TL;
    const float* X  = ch ? XH : XL;
    const float* c2 = ch ? c2H : c2L;

    __shared__ float  ss[32][NCH*TMAX + 1];  // [c_local][n_local*T + s], padded
    __shared__ float4 sc2[N_];

    int tid = threadIdx.x;
    for (int i = tid; i < N_; i += blockDim.x)
        sc2[i] = make_float4(c2[i], c2[N_+i], c2[2*N_+i], c2[3*N_+i]);

    int s  = tid % T;
    int cl = tid / T;
    bool act = (tid < 32*T);
    float a0=0.f,a1=0.f,a2=0.f,a3=0.f;

    for (int nc = 0; nc < N_; nc += NCH){
        int cnt = min(NCH, N_ - nc);
        __syncthreads();
        int tot = 32 * cnt * T;
        for (int L = tid; L < tot; L += blockDim.x){
            int c  = L / (cnt*T);
            int r  = L - c*(cnt*T);
            int sL = r % T;
            int nl = r / T;
            float v = 0.f;
            if (!(ch && sL == 0))
                v = X[(((size_t)b*C_ + cb*32 + c)*N_ + nc + nl)*TL + (ch ? sL-1 : sL)];
            ss[c][nl*T + sL] = v;
        }
        __syncthreads();
        if (act){
            for (int nl = 0; nl < cnt; nl++){
                float v  = ss[cl][nl*T + s];
                float4 w = sc2[nc + nl];
                a0 = fmaf(w.x, v, a0);
                a1 = fmaf(w.y, v, a1);
                a2 = fmaf(w.z, v, a2);
                a3 = fmaf(w.w, v, a3);
            }
        }
    }
    if (act){
        int c = cb*32 + cl;
        g_H[Hidx(ch,0,b,s,c)] = a0;
        g_H[Hidx(ch,1,b,s,c)] = a1;
        g_H[Hidx(ch,2,b,s,c)] = a2;
        g_H[Hidx(ch,3,b,s,c)] = a3;
    }
}

// ---------------- K2: GW_i[b,s,c] = sum_n G_i[b,s,n] * w_i[n,c] -------------
// block = (layer, b) x channel; thread owns column c (128 threads).
__global__ void __launch_bounds__(128) k2_kernel(
    const float* __restrict__ wL, const float* __restrict__ wH)
{
    int ch = blockIdx.y;
    int i  = blockIdx.x % 4;
    int b  = blockIdx.x / 4;
    int T  = ch ? TH : TL;
    const float* w = (ch ? wH : wL) + (size_t)i*N_*C_;

    __shared__ float sg[TMAX*N_];   // 13*307 floats
    int tid = threadIdx.x;
    int base = Gidx(ch,i,b,0,0);
    for (int o = tid; o < T*N_; o += 128) sg[o] = g_G[base + o];
    // zero the unused row for T=12 so the unrolled loop below stays finite
    if (T < TMAX)
        for (int o = tid; o < N_; o += 128) sg[(TMAX-1)*N_ + o] = 0.f;
    __syncthreads();

    float acc[TMAX];
    #pragma unroll
    for (int s = 0; s < TMAX; s++) acc[s] = 0.f;
    int c = tid;
    for (int n = 0; n < N_; n++){
        float wv = __ldg(w + (size_t)n*C_ + c);
        #pragma unroll
        for (int s = 0; s < TMAX; s++)
            acc[s] = fmaf(sg[s*N_ + n], wv, acc[s]);
    }
    int hb = Hidx(ch,i,b,0,0);
    for (int s = 0; s < T; s++) g_GW[hb + s*C_ + c] = acc[s];
}

// ---------------- chain: 4 layers of the tiny per-batch attention chain -----
// grid = (B, 2ch) = 64 blocks; 1 grid barrier per layer for cross-batch BN.
#define PADC 132
__global__ void __launch_bounds__(256) chain_kernel(
    const float* __restrict__ bL, const float* __restrict__ vL,
    const float* __restrict__ gL, const float* __restrict__ beL,
    const float* __restrict__ bH, const float* __restrict__ vH,
    const float* __restrict__ gH, const float* __restrict__ beH)
{
    int b  = blockIdx.x;
    int ch = blockIdx.y;
    int T  = ch ? TH : TL;
    const float* bias = ch ? bH : bL;
    const float* vv   = ch ? vH : vL;
    const float* gam  = ch ? gH : gL;
    const float* bet  = ch ? beH : beL;
    const unsigned nb = 2*B_;

    __shared__ float A[TMAX*TMAX], A2[TMAX*TMAX];
    __shared__ float GWs[TMAX*PADC], Hs[TMAX*PADC];
    __shared__ float f1w[TMAX*PADC], f2s[TMAX*PADC];
    __shared__ float sS[TMAX*TMAX], slog[TMAX*TMAX];
    __shared__ float mu[TMAX], isd[TMAX];

    int tid = threadIdx.x;
    if (tid < T*T){
        int s = tid / T, t = tid % T;
        A[s*TMAX + t] = (s == t) ? 1.f : 0.f;
    }
    __syncthreads();

    for (int i = 0; i < LAYERS; i++){
        int hb = Hidx(ch,i,b,0,0);
        for (int o = tid; o < T*C_; o += 256){
            int s = o / C_, c = o % C_;
            GWs[s*PADC + c] = g_GW[hb + o];
            Hs [s*PADC + c] = g_H [hb + o];
        }
        __syncthreads();

        // f1w[t,c] = sum_s A[s,t]*GW[s,c]; f2[q,c] = sum_s A[s,q]*H[s,c]
        for (int o = tid; o < T*C_; o += 256){
            int t = o / C_, c = o % C_;
            float acc1 = 0.f, acc2 = 0.f;
            for (int s = 0; s < T; s++){
                float a = A[s*TMAX + t];
                acc1 = fmaf(a, GWs[s*PADC + c], acc1);
                acc2 = fmaf(a, Hs [s*PADC + c], acc2);
            }
            f1w[t*PADC + c] = acc1;
            f2s[t*PADC + c] = acc2;
        }
        __syncthreads();

        // scores[t,q] = sigmoid(sum_c f1w[t,c]*f2[q,c] + bias[t,q])
        for (int o = tid; o < T*T; o += 256){
            int t = o / T, q = o % T;
            float acc = bias[(i*T + t)*T + q];
            for (int c = 0; c < C_; c++)
                acc = fmaf(f1w[t*PADC + c], f2s[q*PADC + c], acc);
            sS[t*TMAX + q] = 1.f / (1.f + __expf(-acc));
        }
        __syncthreads();

        // logits[t,q] = sum_k v[t,k]*scores[k,q]  (write to global for BN)
        int buf = i & 1;
        for (int o = tid; o < T*T; o += 256){
            int t = o / T, q = o % T;
            float acc = 0.f;
            for (int k = 0; k < T; k++)
                acc = fmaf(vv[(i*T + t)*T + k], sS[k*TMAX + q], acc);
            slog[t*TMAX + q] = acc;
            g_logits[buf][((ch*B_ + b)*TMAX + t)*TMAX + q] = acc;
        }
        grid_barrier(nb);

        // BN stats per q over (all b, t) for this channel — computed redundantly
        {
            int w = tid / 32, lane = tid % 32;
            for (int q = w; q < T; q += 8){
                float sum = 0.f, sq = 0.f;
                for (int j = lane; j < B_*T; j += 32){
                    int bb = j / T, t = j % T;
                    float val = __ldcg(&g_logits[buf][((ch*B_ + bb)*TMAX + t)*TMAX + q]);
                    sum += val; sq += val*val;
                }
                #pragma unroll
                for (int off = 16; off; off >>= 1){
                    sum += __shfl_down_sync(0xffffffff, sum, off);
                    sq  += __shfl_down_sync(0xffffffff, sq,  off);
                }
                if (lane == 0){
                    float cnt = (float)(B_*T);
                    float m = sum / cnt;
                    float var = sq / cnt - m*m;
                    mu[q]  = m;
                    isd[q] = rsqrtf(var + BN_EPS);
                }
            }
        }
        __syncthreads();

        // normalize + softmax over q (own b, logits already in smem)
        if (tid < T){
            int t = tid;
            float z[TMAX];
            float mx = -1e30f;
            for (int q = 0; q < T; q++){
                float val = (slog[t*TMAX + q] - mu[q]) * isd[q] * gam[i*T + q] + bet[i*T + q];
                z[q] = val;
                mx = fmaxf(mx, val);
            }
            float sum = 0.f;
            for (int q = 0; q < T; q++){ z[q] = __expf(z[q] - mx); sum += z[q]; }
            float inv = 1.f / sum;
            for (int q = 0; q < T; q++) sS[t*TMAX + q] = z[q] * inv;
        }
        __syncthreads();

        // A_new[s,q] = sum_t A[s,t] * S[q,t]
        for (int o = tid; o < T*T; o += 256){
            int s = o / T, q = o % T;
            float acc = 0.f;
            for (int t = 0; t < T; t++)
                acc = fmaf(A[s*TMAX + t], sS[q*TMAX + t], acc);
            A2[s*TMAX + q] = acc;
        }
        __syncthreads();
        for (int o = tid; o < T*T; o += 256)
            A[(o/T)*TMAX + (o%T)] = A2[(o/T)*TMAX + (o%T)];
        __syncthreads();
    }

    if (tid < T)
        g_avec[(ch*B_ + b)*TMAX + tid] = A[tid*TMAX + (T-1)];
}

// ---------------- final: residual + alpha mix, single streaming pass --------
__global__ void __launch_bounds__(256) final_kernel(
    const float* __restrict__ XL, const float* __restrict__ XH,
    const float* __restrict__ alpha, float* __restrict__ out)
{
    int r = blockIdx.x*blockDim.x + threadIdx.x;
    if (r >= B_*C_*N_) return;
    int b = r / (C_*N_);

    const float4* xl4 = (const float4*)(XL + (size_t)r*TL);
    const float4* xh4 = (const float4*)(XH + (size_t)r*TL);
    float xv[12], hv[12];
    *(float4*)&xv[0] = xl4[0]; *(float4*)&xv[4] = xl4[1]; *(float4*)&xv[8] = xl4[2];
    *(float4*)&hv[0] = xh4[0]; *(float4*)&hv[4] = xh4[1]; *(float4*)&hv[8] = xh4[2];

    const float* aL = &g_avec[(0*B_ + b)*TMAX];
    const float* aH = &g_avec[(1*B_ + b)*TMAX];

    float accL = xv[11];           // residual XL[..., -1]
    #pragma unroll
    for (int s = 0; s < 12; s++) accL = fmaf(xv[s], __ldg(aL + s), accL);

    float accH = hv[11];           // residual XH[..., -1]
    #pragma unroll
    for (int u = 0; u < 12; u++) accH = fmaf(hv[u], __ldg(aH + u + 1), accH);
    // (s=0 term of the padded high channel is zero)

    float sa = 1.f / (1.f + expf(-alpha[0]));
    out[r] = sa*accL + (1.f - sa)*accH;
}

// ---------------- launch ----------------------------------------------------
extern "C" void kernel_launch(void* const* d_in, const int* in_sizes, int n_in,
                              void* d_out, int out_size)
{
    const float* XL  = (const float*)d_in[0];
    const float* XH  = (const float*)d_in[1];
    const float* lc1 = (const float*)d_in[2];
    const float* lc2 = (const float*)d_in[3];
    const float* lw  = (const float*)d_in[4];
    const float* lb  = (const float*)d_in[5];
    const float* lv  = (const float*)d_in[6];
    const float* lg  = (const float*)d_in[7];
    const float* lbe = (const float*)d_in[8];
    const float* hc1 = (const float*)d_in[9];
    const float* hc2 = (const float*)d_in[10];
    const float* hw  = (const float*)d_in[11];
    const float* hb  = (const float*)d_in[12];
    const float* hv  = (const float*)d_in[13];
    const float* hg  = (const float*)d_in[14];
    const float* hbe = (const float*)d_in[15];
    const float* alpha = (const float*)d_in[16];
    float* out = (float*)d_out;

    k1a_kernel  <<<dim3(B_*10, 2), 416>>>(XL, XH, lc1, hc1);
    k1b_kernel  <<<dim3(B_*4,  2), 416>>>(XL, XH, lc2, hc2);
    k2_kernel   <<<dim3(B_*4,  2), 128>>>(lw, hw);
    chain_kernel<<<dim3(B_,    2), 256>>>(lb, lv, lg, lbe, hb, hv, hg, hbe);
    int tot = B_*C_*N_;
    final_kernel<<<(tot + 255)/256, 256>>>(XL, XH, alpha, out);
}

// round 2
// speedup vs baseline: 1.3124x; 1.3124x over previous
#include <cuda_runtime.h>
#include <math.h>

#define B_ 32
#define C_ 128
#define N_ 307
#define TL 12
#define TH 13
#define TMAX 13
#define LAYERS 4
#define BN_EPS 1e-5f
#define NT 4            // n-tiles in fused k1
#define NSPAN 77        // ceil(307/4)
#define CCH 8           // c-chunk in fused k1

// ---------------- scratch (static __device__, no allocations) ----------------
__device__ float g_G [2*4*B_*TMAX*N_];             // (ch,layer,b,s,n)
__device__ float g_Hpart[NT*2*4*B_*TMAX*C_];       // (nt,ch,layer,b,s,c)
__device__ float g_GW[2*4*B_*TMAX*C_];             // (ch,layer,b,s,c)
__device__ float g_logits[2][2*B_*TMAX*TMAX];      // double buffered per layer parity
__device__ float g_avec[2*B_*TMAX];                // final A column per (ch,b)
__device__ unsigned g_bar_count;
__device__ unsigned g_bar_gen;

__device__ __forceinline__ int Gidx(int ch,int i,int b,int s,int n){
    return (((ch*4+i)*B_+b)*TMAX+s)*N_+n;
}
__device__ __forceinline__ int Hidx(int ch,int i,int b,int s,int c){
    return (((ch*4+i)*B_+b)*TMAX+s)*C_+c;
}
__device__ __forceinline__ int HPidx(int nt,int ch,int i,int b){
    return ((((nt*2+ch)*4+i)*B_)+b)*TMAX*C_;
}

// grid barrier: 64 co-resident blocks; volatile-load polling (no RMW spin).
__device__ __forceinline__ void grid_barrier(unsigned nb){
    __syncthreads();
    if (threadIdx.x == 0){
        __threadfence();
        volatile unsigned* genp = (volatile unsigned*)&g_bar_gen;
        unsigned gen = *genp;
        unsigned arrived = atomicAdd(&g_bar_count, 1u);
        if (arrived == nb - 1u){
            atomicExch(&g_bar_count, 0u);
            __threadfence();
            *genp = gen + 1u;
        } else {
            while (*genp == gen) { }
        }
    }
    __syncthreads();
}

// ---------------- fused K1: one pass over X producing G and H-partials ------
// block = (b, n-tile) x channel, 512 threads.
// G[ch][i][b][s][n]      = sum_c c1_i[c] * x0[b,c,n,s]   (complete per block)
// Hpart[nt][ch][i][b][s][c] = sum_{n in tile} c2_i[n] * x0[b,c,n,s]
__global__ void __launch_bounds__(512) k1_kernel(
    const float* __restrict__ XL, const float* __restrict__ XH,
    const float* __restrict__ c1L, const float* __restrict__ c1H,
    const float* __restrict__ c2L, const float* __restrict__ c2H)
{
    int ch = blockIdx.y;
    int b  = blockIdx.x / NT;
    int nt = blockIdx.x % NT;
    int T  = ch ? TH : TL;
    int n0 = nt * NSPAN;
    int nspan = min(NSPAN, N_ - n0);
    const float* X  = ch ? XH : XL;
    const float* c1 = ch ? c1H : c1L;
    const float* c2 = ch ? c2H : c2L;

    const int ROWW = NSPAN*TMAX + 7;   // 1008, padded row
    __shared__ float  ss[CCH][NSPAN*TMAX + 7];
    __shared__ float4 sc1[C_];
    __shared__ float4 sc2[NSPAN];

    int tid = threadIdx.x;
    (void)ROWW;
    if (tid < C_)
        sc1[tid] = make_float4(c1[tid], c1[C_+tid], c1[2*C_+tid], c1[3*C_+tid]);
    if (tid >= C_ && tid < C_ + NSPAN){
        int nl = tid - C_;
        if (nl < nspan){
            int n = n0 + nl;
            sc2[nl] = make_float4(c2[n], c2[N_+n], c2[2*N_+n], c2[3*N_+n]);
        }
    }

    // persistent G accumulators: thread owns (n_l, s) pairs p = tid, tid+512
    float ga[2][4];
    #pragma unroll
    for (int u = 0; u < 2; u++)
        #pragma unroll
        for (int i = 0; i < 4; i++) ga[u][i] = 0.f;

    int wid = tid >> 5, lane = tid & 31;
    int pairs = nspan * T;

    for (int chunk = 0; chunk < C_/CCH; chunk++){
        __syncthreads();
        // zero s=0 column for high channel (left pad)
        if (ch){
            for (int j = tid; j < CCH*nspan; j += 512)
                ss[j/nspan][(j - (j/nspan)*nspan)*TH] = 0.f;
        }
        // stage [CCH c][nspan n][12 real s] as float4 streams
        int nf4 = nspan * 3;                 // float4 per c-row
        int totalv = CCH * nf4;
        for (int j = tid; j < totalv; j += 512){
            int cc = j / nf4;
            int r  = j - cc * nf4;
            const float4 v = *(const float4*)(X +
                (((size_t)(b*C_ + chunk*CCH + cc))*N_ + n0)*TL + r*4);
            int e  = r * 4;
            int nl = e / 12;
            int sl = e - nl*12;
            float vv[4] = {v.x, v.y, v.z, v.w};
            #pragma unroll
            for (int k = 0; k < 4; k++){
                int s2 = sl + k, n2 = nl;
                if (s2 >= 12){ s2 -= 12; n2++; }
                ss[cc][n2*T + s2 + ch] = vv[k];
            }
        }
        __syncthreads();

        // G accumulation: add this chunk's 8 c's
        #pragma unroll
        for (int u = 0; u < 2; u++){
            int p = tid + u*512;
            if (p < pairs){
                int nl = p / T, s = p - nl*T;
                #pragma unroll
                for (int cc = 0; cc < CCH; cc++){
                    float v = ss[cc][nl*T + s];
                    float4 w = sc1[chunk*CCH + cc];
                    ga[u][0] = fmaf(w.x, v, ga[u][0]);
                    ga[u][1] = fmaf(w.y, v, ga[u][1]);
                    ga[u][2] = fmaf(w.z, v, ga[u][2]);
                    ga[u][3] = fmaf(w.w, v, ga[u][3]);
                }
            }
        }

        // H: complete n-reduction for this chunk's c's; warp per (cc,s) item
        for (int it = wid; it < CCH*T; it += 16){
            int cc = it / T, s = it - cc*T;
            float a0=0.f, a1=0.f, a2=0.f, a3=0.f;
            for (int nl = lane; nl < nspan; nl += 32){
                float v  = ss[cc][nl*T + s];
                float4 w = sc2[nl];
                a0 = fmaf(w.x, v, a0);
                a1 = fmaf(w.y, v, a1);
                a2 = fmaf(w.z, v, a2);
                a3 = fmaf(w.w, v, a3);
            }
            #pragma unroll
            for (int off = 16; off; off >>= 1){
                a0 += __shfl_down_sync(0xffffffff, a0, off);
                a1 += __shfl_down_sync(0xffffffff, a1, off);
                a2 += __shfl_down_sync(0xffffffff, a2, off);
                a3 += __shfl_down_sync(0xffffffff, a3, off);
            }
            if (lane == 0){
                int c = chunk*CCH + cc;
                g_Hpart[HPidx(nt,ch,0,b) + s*C_ + c] = a0;
                g_Hpart[HPidx(nt,ch,1,b) + s*C_ + c] = a1;
                g_Hpart[HPidx(nt,ch,2,b) + s*C_ + c] = a2;
                g_Hpart[HPidx(nt,ch,3,b) + s*C_ + c] = a3;
            }
        }
    }

    // write G
    #pragma unroll
    for (int u = 0; u < 2; u++){
        int p = tid + u*512;
        if (p < pairs){
            int nl = p / T, s = p - nl*T;
            int n  = n0 + nl;
            g_G[Gidx(ch,0,b,s,n)] = ga[u][0];
            g_G[Gidx(ch,1,b,s,n)] = ga[u][1];
            g_G[Gidx(ch,2,b,s,n)] = ga[u][2];
            g_G[Gidx(ch,3,b,s,n)] = ga[u][3];
        }
    }
}

// ---------------- K2: GW_i[b,s,c] = sum_n G_i[b,s,n] * w_i[n,c] -------------
__global__ void __launch_bounds__(128) k2_kernel(
    const float* __restrict__ wL, const float* __restrict__ wH)
{
    int ch = blockIdx.y;
    int i  = blockIdx.x % 4;
    int b  = blockIdx.x / 4;
    int T  = ch ? TH : TL;
    const float* w = (ch ? wH : wL) + (size_t)i*N_*C_;

    __shared__ float sg[TMAX*N_];
    int tid = threadIdx.x;
    int base = Gidx(ch,i,b,0,0);
    for (int o = tid; o < T*N_; o += 128) sg[o] = g_G[base + o];
    if (T < TMAX)
        for (int o = tid; o < N_; o += 128) sg[(TMAX-1)*N_ + o] = 0.f;
    __syncthreads();

    float acc[TMAX];
    #pragma unroll
    for (int s = 0; s < TMAX; s++) acc[s] = 0.f;
    int c = tid;
    for (int n = 0; n < N_; n++){
        float wv = __ldg(w + (size_t)n*C_ + c);
        #pragma unroll
        for (int s = 0; s < TMAX; s++)
            acc[s] = fmaf(sg[s*N_ + n], wv, acc[s]);
    }
    int hb = Hidx(ch,i,b,0,0);
    for (int s = 0; s < T; s++) g_GW[hb + s*C_ + c] = acc[s];
}

// ---------------- chain: 4 layers of the tiny per-batch attention chain -----
#define PADC 132
__global__ void __launch_bounds__(256) chain_kernel(
    const float* __restrict__ bL, const float* __restrict__ vL,
    const float* __restrict__ gL, const float* __restrict__ beL,
    const float* __restrict__ bH, const float* __restrict__ vH,
    const float* __restrict__ gH, const float* __restrict__ beH)
{
    int b  = blockIdx.x;
    int ch = blockIdx.y;
    int T  = ch ? TH : TL;
    const float* bias = ch ? bH : bL;
    const float* vv   = ch ? vH : vL;
    const float* gam  = ch ? gH : gL;
    const float* bet  = ch ? beH : beL;
    const unsigned nb = 2*B_;

    __shared__ float A[TMAX*TMAX], A2[TMAX*TMAX];
    __shared__ float GWs[TMAX*PADC], Hs[TMAX*PADC];
    __shared__ float f1w[TMAX*PADC], f2s[TMAX*PADC];
    __shared__ float sS[TMAX*TMAX], slog[TMAX*TMAX];
    __shared__ float mu[TMAX], isd[TMAX];

    int tid = threadIdx.x;
    if (tid < T*T){
        int s = tid / T, t = tid % T;
        A[s*TMAX + t] = (s == t) ? 1.f : 0.f;
    }
    __syncthreads();

    for (int i = 0; i < LAYERS; i++){
        int hb = Hidx(ch,i,b,0,0);
        for (int o = tid; o < T*C_; o += 256){
            int s = o / C_, c = o % C_;
            GWs[s*PADC + c] = g_GW[hb + o];
            float h = 0.f;
            #pragma unroll
            for (int nt = 0; nt < NT; nt++)
                h += g_Hpart[HPidx(nt,ch,i,b) + o];
            Hs[s*PADC + c] = h;
        }
        __syncthreads();

        // f1w[t,c] = sum_s A[s,t]*GW[s,c]; f2[q,c] = sum_s A[s,q]*H[s,c]
        for (int o = tid; o < T*C_; o += 256){
            int t = o / C_, c = o % C_;
            float acc1 = 0.f, acc2 = 0.f;
            for (int s = 0; s < T; s++){
                float a = A[s*TMAX + t];
                acc1 = fmaf(a, GWs[s*PADC + c], acc1);
                acc2 = fmaf(a, Hs [s*PADC + c], acc2);
            }
            f1w[t*PADC + c] = acc1;
            f2s[t*PADC + c] = acc2;
        }
        __syncthreads();

        // scores[t,q] = sigmoid(sum_c f1w[t,c]*f2[q,c] + bias[t,q])
        for (int o = tid; o < T*T; o += 256){
            int t = o / T, q = o % T;
            float acc = bias[(i*T + t)*T + q];
            for (int c = 0; c < C_; c++)
                acc = fmaf(f1w[t*PADC + c], f2s[q*PADC + c], acc);
            sS[t*TMAX + q] = 1.f / (1.f + __expf(-acc));
        }
        __syncthreads();

        // logits[t,q] = sum_k v[t,k]*scores[k,q]
        int buf = i & 1;
        for (int o = tid; o < T*T; o += 256){
            int t = o / T, q = o % T;
            float acc = 0.f;
            for (int k = 0; k < T; k++)
                acc = fmaf(vv[(i*T + t)*T + k], sS[k*TMAX + q], acc);
            slog[t*TMAX + q] = acc;
            g_logits[buf][((ch*B_ + b)*TMAX + t)*TMAX + q] = acc;
        }
        grid_barrier(nb);

        // BN stats per q over (all b, t) for this channel — redundant per block
        {
            int w = tid / 32, lane = tid % 32;
            for (int q = w; q < T; q += 8){
                float sum = 0.f, sq = 0.f;
                for (int j = lane; j < B_*T; j += 32){
                    int bb = j / T, t = j % T;
                    float val = __ldcg(&g_logits[buf][((ch*B_ + bb)*TMAX + t)*TMAX + q]);
                    sum += val; sq += val*val;
                }
                #pragma unroll
                for (int off = 16; off; off >>= 1){
                    sum += __shfl_down_sync(0xffffffff, sum, off);
                    sq  += __shfl_down_sync(0xffffffff, sq,  off);
                }
                if (lane == 0){
                    float cnt = (float)(B_*T);
                    float m = sum / cnt;
                    float var = sq / cnt - m*m;
                    mu[q]  = m;
                    isd[q] = rsqrtf(var + BN_EPS);
                }
            }
        }
        __syncthreads();

        // normalize + softmax over q
        if (tid < T){
            int t = tid;
            float z[TMAX];
            float mx = -1e30f;
            for (int q = 0; q < T; q++){
                float val = (slog[t*TMAX + q] - mu[q]) * isd[q] * gam[i*T + q] + bet[i*T + q];
                z[q] = val;
                mx = fmaxf(mx, val);
            }
            float sum = 0.f;
            for (int q = 0; q < T; q++){ z[q] = __expf(z[q] - mx); sum += z[q]; }
            float inv = 1.f / sum;
            for (int q = 0; q < T; q++) sS[t*TMAX + q] = z[q] * inv;
        }
        __syncthreads();

        // A_new[s,q] = sum_t A[s,t] * S[q,t]
        for (int o = tid; o < T*T; o += 256){
            int s = o / T, q = o % T;
            float acc = 0.f;
            for (int t = 0; t < T; t++)
                acc = fmaf(A[s*TMAX + t], sS[q*TMAX + t], acc);
            A2[s*TMAX + q] = acc;
        }
        __syncthreads();
        for (int o = tid; o < T*T; o += 256)
            A[(o/T)*TMAX + (o%T)] = A2[(o/T)*TMAX + (o%T)];
        __syncthreads();
    }

    if (tid < T)
        g_avec[(ch*B_ + b)*TMAX + tid] = A[tid*TMAX + (T-1)];
}

// ---------------- final: residual + alpha mix, single streaming pass --------
__global__ void __launch_bounds__(256) final_kernel(
    const float* __restrict__ XL, const float* __restrict__ XH,
    const float* __restrict__ alpha, float* __restrict__ out)
{
    int r = blockIdx.x*blockDim.x + threadIdx.x;
    if (r >= B_*C_*N_) return;
    int b = r / (C_*N_);

    const float4* xl4 = (const float4*)(XL + (size_t)r*TL);
    const float4* xh4 = (const float4*)(XH + (size_t)r*TL);
    float xv[12], hv[12];
    *(float4*)&xv[0] = xl4[0]; *(float4*)&xv[4] = xl4[1]; *(float4*)&xv[8] = xl4[2];
    *(float4*)&hv[0] = xh4[0]; *(float4*)&hv[4] = xh4[1]; *(float4*)&hv[8] = xh4[2];

    const float* aL = &g_avec[(0*B_ + b)*TMAX];
    const float* aH = &g_avec[(1*B_ + b)*TMAX];

    float accL = xv[11];
    #pragma unroll
    for (int s = 0; s < 12; s++) accL = fmaf(xv[s], __ldg(aL + s), accL);

    float accH = hv[11];
    #pragma unroll
    for (int u = 0; u < 12; u++) accH = fmaf(hv[u], __ldg(aH + u + 1), accH);

    float sa = 1.f / (1.f + expf(-alpha[0]));
    out[r] = sa*accL + (1.f - sa)*accH;
}

// ---------------- launch ----------------------------------------------------
extern "C" void kernel_launch(void* const* d_in, const int* in_sizes, int n_in,
                              void* d_out, int out_size)
{
    const float* XL  = (const float*)d_in[0];
    const float* XH  = (const float*)d_in[1];
    const float* lc1 = (const float*)d_in[2];
    const float* lc2 = (const float*)d_in[3];
    const float* lw  = (const float*)d_in[4];
    const float* lb  = (const float*)d_in[5];
    const float* lv  = (const float*)d_in[6];
    const float* lg  = (const float*)d_in[7];
    const float* lbe = (const float*)d_in[8];
    const float* hc1 = (const float*)d_in[9];
    const float* hc2 = (const float*)d_in[10];
    const float* hw  = (const float*)d_in[11];
    const float* hb  = (const float*)d_in[12];
    const float* hv  = (const float*)d_in[13];
    const float* hg  = (const float*)d_in[14];
    const float* hbe = (const float*)d_in[15];
    const float* alpha = (const float*)d_in[16];
    float* out = (float*)d_out;

    k1_kernel   <<<dim3(B_*NT, 2), 512>>>(XL, XH, lc1, hc1, lc2, hc2);
    k2_kernel   <<<dim3(B_*4,  2), 128>>>(lw, hw);
    chain_kernel<<<dim3(B_,    2), 256>>>(lb, lv, lg, lbe, hb, hv, hg, hbe);
    int tot = B_*C_*N_;
    final_kernel<<<(tot + 255)/256, 256>>>(XL, XH, alpha, out);
}

// round 3
// speedup vs baseline: 1.7407x; 1.3263x over previous
#include <cuda_runtime.h>
#include <math.h>

#define B_ 32
#define C_ 128
#define N_ 307
#define TL 12
#define TH 13
#define TMAX 13
#define LAYERS 4
#define BN_EPS 1e-5f
#define E4 921            // float4 per (b,c) row  (307*12/4)
#define EF 3684           // floats per (b,c) row

// ---------------- scratch (static __device__, no allocations) ----------------
__device__ float4 g_G4[2*4*B_*E4];                 // (ch,layer,b,e) e-flat
__device__ float  g_H [2*4*B_*TMAX*C_];            // (ch,layer,b,s,c) logical s
__device__ float  g_GW[2*4*B_*TMAX*C_];            // (ch,layer,b,s,c) logical s
__device__ float  g_logits[2][2*B_*TMAX*TMAX];     // double buffered per layer parity
__device__ float  g_avec[2*B_*TMAX];               // final A column per (ch,b)
__device__ unsigned g_bar_count;
__device__ unsigned g_bar_gen;

__device__ __forceinline__ int Hidx(int ch,int i,int b,int s,int c){
    return (((ch*4+i)*B_+b)*TMAX+s)*C_+c;
}

// grid barrier: 64 co-resident blocks; volatile-load polling.
__device__ __forceinline__ void grid_barrier(unsigned nb){
    __syncthreads();
    if (threadIdx.x == 0){
        __threadfence();
        volatile unsigned* genp = (volatile unsigned*)&g_bar_gen;
        unsigned gen = *genp;
        unsigned arrived = atomicAdd(&g_bar_count, 1u);
        if (arrived == nb - 1u){
            atomicExch(&g_bar_count, 0u);
            __threadfence();
            *genp = gen + 1u;
        } else {
            while (*genp == gen) { }
        }
    }
    __syncthreads();
}

// ---------------- kA: dual-role single pass over X --------------------------
// grid.x = 64 groups * 10 blocks. Per (b,ch) group: roles 0..7 = H (16 c each),
// roles 8..9 = G (e-range halves). Same-group blocks stream the same X slab
// concurrently -> L2 reuse.
#define SSPAD 396
__global__ void __launch_bounds__(256) kA_kernel(
    const float* __restrict__ XL, const float* __restrict__ XH,
    const float* __restrict__ c1L, const float* __restrict__ c1H,
    const float* __restrict__ c2L, const float* __restrict__ c2H)
{
    int bid   = blockIdx.x;
    int group = bid / 10;
    int role  = bid - group*10;
    int b  = group >> 1;
    int ch = group & 1;
    const float4* X4 = (const float4*)(ch ? XH : XL);
    int tid = threadIdx.x;

    __shared__ union {
        struct { float ss[16][SSPAD]; float4 sc2[N_]; } h;
        struct { float4 sc1[C_]; } g;
    } sm;

    if (role >= 8){
        // ================= G role: G[ch][i][b][e] = sum_c c1_i[c]*X[b,c,e] ==
        int eh = role - 8;
        const float* c1 = ch ? c1H : c1L;
        if (tid < C_)
            sm.g.sc1[tid] = make_float4(c1[tid], c1[C_+tid], c1[2*C_+tid], c1[3*C_+tid]);
        __syncthreads();

        int e0 = eh*464 + tid;
        int e1 = e0 + 256;
        bool ok1 = (e1 < (eh ? E4 : 464));

        float4 a0[4], a1[4];
        #pragma unroll
        for (int i = 0; i < 4; i++){
            a0[i] = make_float4(0.f,0.f,0.f,0.f);
            a1[i] = make_float4(0.f,0.f,0.f,0.f);
        }

        size_t rb = (size_t)b * C_ * E4;
        #pragma unroll 4
        for (int c = 0; c < C_; c++){
            float4 w  = sm.g.sc1[c];
            float4 v0 = X4[rb + (size_t)c*E4 + e0];
            a0[0].x = fmaf(w.x, v0.x, a0[0].x); a0[0].y = fmaf(w.x, v0.y, a0[0].y);
            a0[0].z = fmaf(w.x, v0.z, a0[0].z); a0[0].w = fmaf(w.x, v0.w, a0[0].w);
            a0[1].x = fmaf(w.y, v0.x, a0[1].x); a0[1].y = fmaf(w.y, v0.y, a0[1].y);
            a0[1].z = fmaf(w.y, v0.z, a0[1].z); a0[1].w = fmaf(w.y, v0.w, a0[1].w);
            a0[2].x = fmaf(w.z, v0.x, a0[2].x); a0[2].y = fmaf(w.z, v0.y, a0[2].y);
            a0[2].z = fmaf(w.z, v0.z, a0[2].z); a0[2].w = fmaf(w.z, v0.w, a0[2].w);
            a0[3].x = fmaf(w.w, v0.x, a0[3].x); a0[3].y = fmaf(w.w, v0.y, a0[3].y);
            a0[3].z = fmaf(w.w, v0.z, a0[3].z); a0[3].w = fmaf(w.w, v0.w, a0[3].w);
            if (ok1){
                float4 v1 = X4[rb + (size_t)c*E4 + e1];
                a1[0].x = fmaf(w.x, v1.x, a1[0].x); a1[0].y = fmaf(w.x, v1.y, a1[0].y);
                a1[0].z = fmaf(w.x, v1.z, a1[0].z); a1[0].w = fmaf(w.x, v1.w, a1[0].w);
                a1[1].x = fmaf(w.y, v1.x, a1[1].x); a1[1].y = fmaf(w.y, v1.y, a1[1].y);
                a1[1].z = fmaf(w.y, v1.z, a1[1].z); a1[1].w = fmaf(w.y, v1.w, a1[1].w);
                a1[2].x = fmaf(w.z, v1.x, a1[2].x); a1[2].y = fmaf(w.z, v1.y, a1[2].y);
                a1[2].z = fmaf(w.z, v1.z, a1[2].z); a1[2].w = fmaf(w.z, v1.w, a1[2].w);
                a1[3].x = fmaf(w.w, v1.x, a1[3].x); a1[3].y = fmaf(w.w, v1.y, a1[3].y);
                a1[3].z = fmaf(w.w, v1.z, a1[3].z); a1[3].w = fmaf(w.w, v1.w, a1[3].w);
            }
        }
        #pragma unroll
        for (int i = 0; i < 4; i++){
            size_t gb = (size_t)((ch*4+i)*B_ + b) * E4;
            g_G4[gb + e0] = a0[i];
            if (ok1) g_G4[gb + e1] = a1[i];
        }
    } else {
        // ================= H role: H[ch][i][b][s][c] = sum_n c2_i[n]*X[b,c,n,s]
        int ct = role;
        int cbase = ct*16;
        const float* c2 = ch ? c2H : c2L;
        for (int t = tid; t < N_; t += 256)
            sm.h.sc2[t] = make_float4(c2[t], c2[N_+t], c2[2*N_+t], c2[3*N_+t]);

        int cl = tid / 12, s = tid - cl*12;
        bool act = (tid < 192);
        float acc0=0.f, acc1=0.f, acc2=0.f, acc3=0.f;

        for (int nk = 0; nk < 10; nk++){
            int n0 = nk*32;
            int nn = min(32, N_ - n0);         // 32 or 19
            int f4cnt = nn*3;                  // 96 or 57
            __syncthreads();
            #pragma unroll
            for (int j0 = 0; j0 < 16*96; j0 += 256){
                int j = j0 + tid;
                int c = j / 96, r = j - c*96;  // compile-time divisor
                if (r < f4cnt){
                    float4 v = X4[(size_t)(b*C_ + cbase + c)*E4 + nk*96 + r];
                    *(float4*)&sm.h.ss[c][r*4] = v;
                }
            }
            __syncthreads();
            if (act){
                for (int nl = 0; nl < nn; nl++){
                    float  v = sm.h.ss[cl][nl*12 + s];
                    float4 w = sm.h.sc2[n0 + nl];
                    acc0 = fmaf(w.x, v, acc0);
                    acc1 = fmaf(w.y, v, acc1);
                    acc2 = fmaf(w.z, v, acc2);
                    acc3 = fmaf(w.w, v, acc3);
                }
            }
        }
        if (act){
            int c  = cbase + cl;
            int sl = s + ch;                    // logical s (high channel shifted)
            g_H[Hidx(ch,0,b,sl,c)] = acc0;
            g_H[Hidx(ch,1,b,sl,c)] = acc1;
            g_H[Hidx(ch,2,b,sl,c)] = acc2;
            g_H[Hidx(ch,3,b,sl,c)] = acc3;
        }
        if (ch && tid < 16){
            #pragma unroll
            for (int i = 0; i < 4; i++)
                g_H[Hidx(1,i,b,0,cbase + tid)] = 0.f;   // left-pad row
        }
    }
}

// ---------------- K2: GW_i[b,s,c] = sum_n G_i[b,s,n] * w_i[n,c] -------------
__global__ void __launch_bounds__(128) k2_kernel(
    const float* __restrict__ wL, const float* __restrict__ wH)
{
    int ch = blockIdx.y;
    int i  = blockIdx.x % 4;
    int b  = blockIdx.x / 4;
    int T  = ch ? TH : TL;
    const float* w = (ch ? wH : wL) + (size_t)i*N_*C_;

    __shared__ float sg[EF];
    int tid = threadIdx.x;
    const float* G = (const float*)g_G4 + (size_t)((ch*4+i)*B_ + b)*EF;
    for (int o = tid; o < EF; o += 128) sg[o] = G[o];
    __syncthreads();

    float acc[TMAX];
    #pragma unroll
    for (int s = 0; s < TMAX; s++) acc[s] = 0.f;
    int c = tid;
    if (ch == 0){
        for (int n = 0; n < N_; n++){
            float wv = __ldg(w + n*C_ + c);
            #pragma unroll
            for (int s = 0; s < 12; s++)
                acc[s] = fmaf(sg[n*12+s], wv, acc[s]);
        }
    } else {
        for (int n = 0; n < N_; n++){
            float wv = __ldg(w + n*C_ + c);
            #pragma unroll
            for (int s = 0; s < 12; s++)
                acc[s+1] = fmaf(sg[n*12+s], wv, acc[s+1]);
        }
    }
    int hb = Hidx(ch,i,b,0,0);
    for (int s = 0; s < T; s++) g_GW[hb + s*C_ + c] = acc[s];
}

// ---------------- chain: 4 layers of the tiny per-batch attention chain -----
#define PADC 132
__global__ void __launch_bounds__(256) chain_kernel(
    const float* __restrict__ bL, const float* __restrict__ vL,
    const float* __restrict__ gL, const float* __restrict__ beL,
    const float* __restrict__ bH, const float* __restrict__ vH,
    const float* __restrict__ gH, const float* __restrict__ beH)
{
    int b  = blockIdx.x;
    int ch = blockIdx.y;
    int T  = ch ? TH : TL;
    const float* bias = ch ? bH : bL;
    const float* vv   = ch ? vH : vL;
    const float* gam  = ch ? gH : gL;
    const float* bet  = ch ? beH : beL;
    const unsigned nb = 2*B_;

    __shared__ float A[TMAX*TMAX], A2[TMAX*TMAX];
    __shared__ float GWs[TMAX*PADC], Hs[TMAX*PADC];
    __shared__ float f1w[TMAX*PADC], f2s[TMAX*PADC];
    __shared__ float sS[TMAX*TMAX], slog[TMAX*TMAX];
    __shared__ float mu[TMAX], isd[TMAX];

    int tid = threadIdx.x;
    if (tid < T*T){
        int s = tid / T, t = tid % T;
        A[s*TMAX + t] = (s == t) ? 1.f : 0.f;
    }
    __syncthreads();

    for (int i = 0; i < LAYERS; i++){
        int hb = Hidx(ch,i,b,0,0);
        for (int o = tid; o < T*C_; o += 256){
            int s = o / C_, c = o - s*C_;
            GWs[s*PADC + c] = g_GW[hb + o];
            Hs [s*PADC + c] = g_H [hb + o];
        }
        __syncthreads();

        // f1w[t,c] = sum_s A[s,t]*GW[s,c]; f2[q,c] = sum_s A[s,q]*H[s,c]
        for (int o = tid; o < T*C_; o += 256){
            int t = o / C_, c = o - t*C_;
            float acc1 = 0.f, acc2 = 0.f;
            for (int s = 0; s < T; s++){
                float a = A[s*TMAX + t];
                acc1 = fmaf(a, GWs[s*PADC + c], acc1);
                acc2 = fmaf(a, Hs [s*PADC + c], acc2);
            }
            f1w[t*PADC + c] = acc1;
            f2s[t*PADC + c] = acc2;
        }
        __syncthreads();

        // scores[t,q] = sigmoid(sum_c f1w[t,c]*f2[q,c] + bias[t,q])
        for (int o = tid; o < T*T; o += 256){
            int t = o / T, q = o - t*T;
            float acc = bias[(i*T + t)*T + q];
            for (int c = 0; c < C_; c++)
                acc = fmaf(f1w[t*PADC + c], f2s[q*PADC + c], acc);
            sS[t*TMAX + q] = 1.f / (1.f + __expf(-acc));
        }
        __syncthreads();

        // logits[t,q] = sum_k v[t,k]*scores[k,q]
        int buf = i & 1;
        for (int o = tid; o < T*T; o += 256){
            int t = o / T, q = o - t*T;
            float acc = 0.f;
            for (int k = 0; k < T; k++)
                acc = fmaf(vv[(i*T + t)*T + k], sS[k*TMAX + q], acc);
            slog[t*TMAX + q] = acc;
            g_logits[buf][((ch*B_ + b)*TMAX + t)*TMAX + q] = acc;
        }
        grid_barrier(nb);

        // BN stats per q over (all b, t) for this channel — redundant per block
        {
            int w = tid / 32, lane = tid % 32;
            for (int q = w; q < T; q += 8){
                float sum = 0.f, sq = 0.f;
                for (int j = lane; j < B_*T; j += 32){
                    int bb = j / T, t = j - bb*T;
                    float val = __ldcg(&g_logits[buf][((ch*B_ + bb)*TMAX + t)*TMAX + q]);
                    sum += val; sq += val*val;
                }
                #pragma unroll
                for (int off = 16; off; off >>= 1){
                    sum += __shfl_down_sync(0xffffffff, sum, off);
                    sq  += __shfl_down_sync(0xffffffff, sq,  off);
                }
                if (lane == 0){
                    float cnt = (float)(B_*T);
                    float m = sum / cnt;
                    float var = sq / cnt - m*m;
                    mu[q]  = m;
                    isd[q] = rsqrtf(var + BN_EPS);
                }
            }
        }
        __syncthreads();

        // normalize + softmax over q
        if (tid < T){
            int t = tid;
            float z[TMAX];
            float mx = -1e30f;
            for (int q = 0; q < T; q++){
                float val = (slog[t*TMAX + q] - mu[q]) * isd[q] * gam[i*T + q] + bet[i*T + q];
                z[q] = val;
                mx = fmaxf(mx, val);
            }
            float sum = 0.f;
            for (int q = 0; q < T; q++){ z[q] = __expf(z[q] - mx); sum += z[q]; }
            float inv = 1.f / sum;
            for (int q = 0; q < T; q++) sS[t*TMAX + q] = z[q] * inv;
        }
        __syncthreads();

        // A_new[s,q] = sum_t A[s,t] * S[q,t]
        for (int o = tid; o < T*T; o += 256){
            int s = o / T, q = o - s*T;
            float acc = 0.f;
            for (int t = 0; t < T; t++)
                acc = fmaf(A[s*TMAX + t], sS[q*TMAX + t], acc);
            A2[s*TMAX + q] = acc;
        }
        __syncthreads();
        for (int o = tid; o < T*T; o += 256)
            A[(o/T)*TMAX + (o%T)] = A2[(o/T)*TMAX + (o%T)];
        __syncthreads();
    }

    if (tid < T)
        g_avec[(ch*B_ + b)*TMAX + tid] = A[tid*TMAX + (T-1)];
}

// ---------------- final: residual + alpha mix, single streaming pass --------
__global__ void __launch_bounds__(256) final_kernel(
    const float* __restrict__ XL, const float* __restrict__ XH,
    const float* __restrict__ alpha, float* __restrict__ out)
{
    int r = blockIdx.x*blockDim.x + threadIdx.x;
    if (r >= B_*C_*N_) return;
    int b = r / (C_*N_);

    const float4* xl4 = (const float4*)(XL + (size_t)r*TL);
    const float4* xh4 = (const float4*)(XH + (size_t)r*TL);
    float xv[12], hv[12];
    *(float4*)&xv[0] = xl4[0]; *(float4*)&xv[4] = xl4[1]; *(float4*)&xv[8] = xl4[2];
    *(float4*)&hv[0] = xh4[0]; *(float4*)&hv[4] = xh4[1]; *(float4*)&hv[8] = xh4[2];

    const float* aL = &g_avec[(0*B_ + b)*TMAX];
    const float* aH = &g_avec[(1*B_ + b)*TMAX];

    float accL = xv[11];
    #pragma unroll
    for (int s = 0; s < 12; s++) accL = fmaf(xv[s], __ldg(aL + s), accL);

    float accH = hv[11];
    #pragma unroll
    for (int u = 0; u < 12; u++) accH = fmaf(hv[u], __ldg(aH + u + 1), accH);

    float sa = 1.f / (1.f + expf(-alpha[0]));
    out[r] = sa*accL + (1.f - sa)*accH;
}

// ---------------- launch ----------------------------------------------------
extern "C" void kernel_launch(void* const* d_in, const int* in_sizes, int n_in,
                              void* d_out, int out_size)
{
    const float* XL  = (const float*)d_in[0];
    const float* XH  = (const float*)d_in[1];
    const float* lc1 = (const float*)d_in[2];
    const float* lc2 = (const float*)d_in[3];
    const float* lw  = (const float*)d_in[4];
    const float* lb  = (const float*)d_in[5];
    const float* lv  = (const float*)d_in[6];
    const float* lg  = (const float*)d_in[7];
    const float* lbe = (const float*)d_in[8];
    const float* hc1 = (const float*)d_in[9];
    const float* hc2 = (const float*)d_in[10];
    const float* hw  = (const float*)d_in[11];
    const float* hb  = (const float*)d_in[12];
    const float* hv  = (const float*)d_in[13];
    const float* hg  = (const float*)d_in[14];
    const float* hbe = (const float*)d_in[15];
    const float* alpha = (const float*)d_in[16];
    float* out = (float*)d_out;

    kA_kernel   <<<640, 256>>>(XL, XH, lc1, hc1, lc2, hc2);
    k2_kernel   <<<dim3(B_*4, 2), 128>>>(lw, hw);
    chain_kernel<<<dim3(B_,   2), 256>>>(lb, lv, lg, lbe, hb, hv, hg, hbe);
    int tot = B_*C_*N_;
    final_kernel<<<(tot + 255)/256, 256>>>(XL, XH, alpha, out);
}

// round 4
// speedup vs baseline: 2.3155x; 1.3302x over previous
#include <cuda_runtime.h>
#include <math.h>

#define B_ 32
#define C_ 128
#define N_ 307
#define TL 12
#define TH 13
#define TMAX 13
#define LAYERS 4
#define BN_EPS 1e-5f
#define E4 921            // float4 per (b,c) row  (307*12/4)
#define EF 3684           // floats per (b,c) row
#define NBLOCKS 512
#define PADC 132

// ---------------- scratch (static __device__, no allocations) ----------------
__device__ float g_Gpart[8*2*4*B_*EF];           // (cb,ch,layer,b,e) 30.2 MB
__device__ float g_H [2*4*B_*TMAX*C_];           // (ch,layer,b,sl,c)
__device__ float g_GWpart[2*2*4*B_*TMAX*C_];     // (half,ch,layer,b,sl,c)
__device__ float g_logits[2][2*B_*TMAX*TMAX];    // double buffered per layer parity
__device__ float g_avec[2*B_*TMAX];              // final A column per (ch,b)
__device__ unsigned g_bar_count;
__device__ unsigned g_bar_gen;

__device__ __forceinline__ int GPidx(int cb,int ch,int i,int b){
    return (((cb*2+ch)*4+i)*B_+b)*EF;
}
__device__ __forceinline__ int Hidx(int ch,int i,int b,int s,int c){
    return (((ch*4+i)*B_+b)*TMAX+s)*C_+c;
}
__device__ __forceinline__ int GWPidx(int half,int ch,int i,int b){
    return (((half*2+ch)*4+i)*B_+b)*TMAX*C_;
}

// grid barrier over all NBLOCKS co-resident blocks
__device__ __forceinline__ void gbar(){
    __threadfence();
    __syncthreads();
    if (threadIdx.x == 0){
        volatile unsigned* genp = (volatile unsigned*)&g_bar_gen;
        unsigned gen = *genp;
        if (atomicAdd(&g_bar_count, 1u) == NBLOCKS - 1u){
            atomicExch(&g_bar_count, 0u);
            __threadfence();
            *genp = gen + 1u;
        } else {
            while (*genp == gen) { __nanosleep(32); }
        }
    }
    __syncthreads();
}

struct SMa { float ss[16][396]; float4 sc2[N_]; float4 sc1h[16]; };
struct SMb { float sg[1856]; float red[1536]; };
struct SMc { float A[TMAX*TMAX], A2[TMAX*TMAX];
             float GWs[TMAX*PADC], Hs[TMAX*PADC], f1w[TMAX*PADC], f2s[TMAX*PADC];
             float sS[TMAX*TMAX], slog[TMAX*TMAX], mu[TMAX], isd[TMAX]; };
union SMU { SMa a; SMb b; SMc c; };

__global__ void __launch_bounds__(256, 4) mega_kernel(
    const float* __restrict__ XL,  const float* __restrict__ XH,
    const float* __restrict__ c1L, const float* __restrict__ c2L,
    const float* __restrict__ wL,  const float* __restrict__ bL,
    const float* __restrict__ vL,  const float* __restrict__ gL,
    const float* __restrict__ beL,
    const float* __restrict__ c1H, const float* __restrict__ c2H,
    const float* __restrict__ wH,  const float* __restrict__ bH,
    const float* __restrict__ vH,  const float* __restrict__ gH,
    const float* __restrict__ beH,
    const float* __restrict__ alpha, float* __restrict__ out)
{
    __shared__ SMU sm;
    int bid = blockIdx.x, tid = threadIdx.x;

    // ================= Phase A: stream X once; produce H (complete) and G partials
    {
        int group = bid >> 3, cb = bid & 7;
        int b = group >> 1, ch = group & 1;
        int cbase = cb * 16;
        const float4* X4 = (const float4*)(ch ? XH : XL);
        const float* c1 = ch ? c1H : c1L;
        const float* c2 = ch ? c2H : c2L;

        for (int t = tid; t < N_; t += 256)
            sm.a.sc2[t] = make_float4(c2[t], c2[N_+t], c2[2*N_+t], c2[3*N_+t]);
        if (tid < 16){
            int c = cbase + tid;
            sm.a.sc1h[tid] = make_float4(c1[c], c1[C_+c], c1[2*C_+c], c1[3*C_+c]);
        }

        int cl = tid / 12, s12 = tid - cl*12;
        bool act = (tid < 192);
        float h0=0.f, h1=0.f, h2=0.f, h3=0.f;

        for (int nk = 0; nk < 10; nk++){
            int n0 = nk*32;
            int nn = min(32, N_ - n0);          // 32 or 19
            int f4cnt = nn*3;
            __syncthreads();
            #pragma unroll
            for (int j0 = 0; j0 < 1536; j0 += 256){
                int j = j0 + tid;
                int c = j / 96, r = j - c*96;    // compile-time divisor
                if (r < f4cnt)
                    *(float4*)&sm.a.ss[c][r*4] =
                        X4[(size_t)(b*C_ + cbase + c)*E4 + nk*96 + r];
            }
            __syncthreads();

            // H accumulate (n-reduction over this chunk, thread per (c_local,s))
            if (act){
                for (int nl = 0; nl < nn; nl++){
                    float  v = sm.a.ss[cl][nl*12 + s12];
                    float4 w = sm.a.sc2[n0 + nl];
                    h0 = fmaf(w.x, v, h0);
                    h1 = fmaf(w.y, v, h1);
                    h2 = fmaf(w.z, v, h2);
                    h3 = fmaf(w.w, v, h3);
                }
            }
            // G partial (c-reduction over my 16 c, thread per element e)
            int jmax = nn*12;
            for (int j = tid; j < jmax; j += 256){
                int nl = j / 12, sg_ = j - nl*12;
                float p0=0.f, p1=0.f, p2=0.f, p3=0.f;
                #pragma unroll
                for (int cc = 0; cc < 16; cc++){
                    float  v = sm.a.ss[cc][nl*12 + sg_];
                    float4 w = sm.a.sc1h[cc];
                    p0 = fmaf(w.x, v, p0);
                    p1 = fmaf(w.y, v, p1);
                    p2 = fmaf(w.z, v, p2);
                    p3 = fmaf(w.w, v, p3);
                }
                int e = nk*384 + j;
                g_Gpart[GPidx(cb,ch,0,b) + e] = p0;
                g_Gpart[GPidx(cb,ch,1,b) + e] = p1;
                g_Gpart[GPidx(cb,ch,2,b) + e] = p2;
                g_Gpart[GPidx(cb,ch,3,b) + e] = p3;
            }
        }
        if (act){
            int c = cbase + cl, sl = s12 + ch;    // logical s (high shifted)
            g_H[Hidx(ch,0,b,sl,c)] = h0;
            g_H[Hidx(ch,1,b,sl,c)] = h1;
            g_H[Hidx(ch,2,b,sl,c)] = h2;
            g_H[Hidx(ch,3,b,sl,c)] = h3;
        }
        if (ch && tid < 16){
            #pragma unroll
            for (int i = 0; i < 4; i++)
                g_H[Hidx(1,i,b,0,cbase + tid)] = 0.f;  // left-pad row
        }
    }
    gbar();

    // ================= Phase B: GW_i[b,s,c] = sum_n G_i[b,s,n] * w_i[n,c]
    // 512 blocks = (half n-range) x (ch,i,b)
    {
        int half = bid & 1;
        int b  = (bid >> 1) & 31;
        int i  = (bid >> 6) & 3;
        int ch =  bid >> 8;
        int nstart = half ? 154 : 0;
        int ncnt   = half ? 153 : 154;
        int e0 = nstart*12, ecnt = ncnt*12;

        for (int j = tid; j < ecnt; j += 256){
            float v = 0.f;
            #pragma unroll
            for (int cb = 0; cb < 8; cb++)
                v += g_Gpart[GPidx(cb,ch,i,b) + e0 + j];
            sm.b.sg[j] = v;
        }
        __syncthreads();

        int c  = tid & 127;
        int nh = tid >> 7;
        const float* w = (ch ? wH : wL) + (size_t)i*N_*C_;
        float acc[12];
        #pragma unroll
        for (int s = 0; s < 12; s++) acc[s] = 0.f;
        int nmid = ncnt >> 1;
        int nA = nh ? nmid : 0;
        int nB = nh ? ncnt : nmid;
        for (int nl = nA; nl < nB; nl++){
            float wv = __ldg(w + (size_t)(nstart + nl)*C_ + c);
            #pragma unroll
            for (int s = 0; s < 12; s++)
                acc[s] = fmaf(sm.b.sg[nl*12 + s], wv, acc[s]);
        }
        if (nh){
            #pragma unroll
            for (int s = 0; s < 12; s++) sm.b.red[s*128 + c] = acc[s];
        }
        __syncthreads();
        if (!nh){
            int base = GWPidx(half,ch,i,b);
            #pragma unroll
            for (int s = 0; s < 12; s++){
                float v = acc[s] + sm.b.red[s*128 + c];
                g_GWpart[base + (s + ch)*C_ + c] = v;
            }
            if (ch) g_GWpart[base + c] = 0.f;     // logical s=0 pad row
        }
    }
    gbar();

    // ================= Phase C: 4-layer tiny attention chain (64 active blocks)
    {
        bool active = (bid < 64);
        int ch = bid & 1, b = bid >> 1;
        int T  = ch ? TH : TL;
        const float* bias = ch ? bH  : bL;
        const float* vvp  = ch ? vH  : vL;
        const float* gam  = ch ? gH  : gL;
        const float* bet  = ch ? beH : beL;

        if (active && tid < T*T){
            int s = tid / T, t = tid % T;
            sm.c.A[s*TMAX + t] = (s == t) ? 1.f : 0.f;
        }
        __syncthreads();

        for (int i = 0; i < LAYERS; i++){
            if (active){
                int hb = Hidx(ch,i,b,0,0);
                int g0 = GWPidx(0,ch,i,b), g1 = GWPidx(1,ch,i,b);
                for (int o = tid; o < T*C_; o += 256){
                    int s = o / C_, c = o - s*C_;
                    sm.c.GWs[s*PADC + c] = g_GWpart[g0 + o] + g_GWpart[g1 + o];
                    sm.c.Hs [s*PADC + c] = g_H[hb + o];
                }
                __syncthreads();

                // f1w[t,c] = sum_s A[s,t]*GW[s,c]; f2[q,c] = sum_s A[s,q]*H[s,c]
                for (int o = tid; o < T*C_; o += 256){
                    int t = o / C_, c = o - t*C_;
                    float a1 = 0.f, a2 = 0.f;
                    for (int s = 0; s < T; s++){
                        float a = sm.c.A[s*TMAX + t];
                        a1 = fmaf(a, sm.c.GWs[s*PADC + c], a1);
                        a2 = fmaf(a, sm.c.Hs [s*PADC + c], a2);
                    }
                    sm.c.f1w[t*PADC + c] = a1;
                    sm.c.f2s[t*PADC + c] = a2;
                }
                __syncthreads();

                // scores[t,q] = sigmoid(f1w . f2 + bias)
                for (int o = tid; o < T*T; o += 256){
                    int t = o / T, q = o - t*T;
                    float acc = bias[(i*T + t)*T + q];
                    for (int c = 0; c < C_; c++)
                        acc = fmaf(sm.c.f1w[t*PADC + c], sm.c.f2s[q*PADC + c], acc);
                    sm.c.sS[t*TMAX + q] = 1.f / (1.f + __expf(-acc));
                }
                __syncthreads();

                // logits[t,q] = sum_k v[t,k]*scores[k,q]
                int buf = i & 1;
                for (int o = tid; o < T*T; o += 256){
                    int t = o / T, q = o - t*T;
                    float acc = 0.f;
                    for (int k = 0; k < T; k++)
                        acc = fmaf(vvp[(i*T + t)*T + k], sm.c.sS[k*TMAX + q], acc);
                    sm.c.slog[t*TMAX + q] = acc;
                    g_logits[buf][((ch*B_ + b)*TMAX + t)*TMAX + q] = acc;
                }
            }
            gbar();
            if (active){
                int buf = i & 1;
                // BN stats per q over (all b, t) — redundant per block
                int w = tid / 32, lane = tid % 32;
                for (int q = w; q < T; q += 8){
                    float sum = 0.f, sq = 0.f;
                    for (int j = lane; j < B_*T; j += 32){
                        int bb = j / T, t = j - bb*T;
                        float val = __ldcg(&g_logits[buf][((ch*B_ + bb)*TMAX + t)*TMAX + q]);
                        sum += val; sq += val*val;
                    }
                    #pragma unroll
                    for (int off = 16; off; off >>= 1){
                        sum += __shfl_down_sync(0xffffffff, sum, off);
                        sq  += __shfl_down_sync(0xffffffff, sq,  off);
                    }
                    if (lane == 0){
                        float cnt = (float)(B_*T);
                        float m = sum / cnt;
                        float var = sq / cnt - m*m;
                        sm.c.mu[q]  = m;
                        sm.c.isd[q] = rsqrtf(var + BN_EPS);
                    }
                }
                __syncthreads();

                // normalize + softmax over q
                if (tid < T){
                    int t = tid;
                    float z[TMAX];
                    float mx = -1e30f;
                    for (int q = 0; q < T; q++){
                        float val = (sm.c.slog[t*TMAX + q] - sm.c.mu[q]) * sm.c.isd[q]
                                    * gam[i*T + q] + bet[i*T + q];
                        z[q] = val;
                        mx = fmaxf(mx, val);
                    }
                    float sum = 0.f;
                    for (int q = 0; q < T; q++){ z[q] = __expf(z[q] - mx); sum += z[q]; }
                    float inv = 1.f / sum;
                    for (int q = 0; q < T; q++) sm.c.sS[t*TMAX + q] = z[q] * inv;
                }
                __syncthreads();

                // A_new[s,q] = sum_t A[s,t] * S[q,t]
                for (int o = tid; o < T*T; o += 256){
                    int s = o / T, q = o - s*T;
                    float acc = 0.f;
                    for (int t = 0; t < T; t++)
                        acc = fmaf(sm.c.A[s*TMAX + t], sm.c.sS[q*TMAX + t], acc);
                    sm.c.A2[s*TMAX + q] = acc;
                }
                __syncthreads();
                for (int o = tid; o < T*T; o += 256)
                    sm.c.A[(o/T)*TMAX + (o%T)] = sm.c.A2[(o/T)*TMAX + (o%T)];
                __syncthreads();
            }
        }
        if (active && tid < T)
            g_avec[(ch*B_ + b)*TMAX + tid] = sm.c.A[tid*TMAX + (T-1)];
    }
    gbar();

    // ================= Phase D: residual + alpha mix, streaming, all blocks
    {
        float sa = 1.f / (1.f + expf(-alpha[0]));
        float sb = 1.f - sa;
        const int total = B_*C_*N_;
        for (int r = bid*256 + tid; r < total; r += NBLOCKS*256){
            int b = r / (C_*N_);
            const float4* xl4 = (const float4*)(XL + (size_t)r*TL);
            const float4* xh4 = (const float4*)(XH + (size_t)r*TL);
            float4 l0 = xl4[0], l1 = xl4[1], l2 = xl4[2];
            float4 h0 = xh4[0], h1 = xh4[1], h2 = xh4[2];
            const float* aL = &g_avec[(0*B_ + b)*TMAX];
            const float* aH = &g_avec[(1*B_ + b)*TMAX];

            float accL = l2.w;
            accL = fmaf(l0.x, __ldg(aL+0),  accL);
            accL = fmaf(l0.y, __ldg(aL+1),  accL);
            accL = fmaf(l0.z, __ldg(aL+2),  accL);
            accL = fmaf(l0.w, __ldg(aL+3),  accL);
            accL = fmaf(l1.x, __ldg(aL+4),  accL);
            accL = fmaf(l1.y, __ldg(aL+5),  accL);
            accL = fmaf(l1.z, __ldg(aL+6),  accL);
            accL = fmaf(l1.w, __ldg(aL+7),  accL);
            accL = fmaf(l2.x, __ldg(aL+8),  accL);
            accL = fmaf(l2.y, __ldg(aL+9),  accL);
            accL = fmaf(l2.z, __ldg(aL+10), accL);
            accL = fmaf(l2.w, __ldg(aL+11), accL);

            float accH = h2.w;
            accH = fmaf(h0.x, __ldg(aH+1),  accH);
            accH = fmaf(h0.y, __ldg(aH+2),  accH);
            accH = fmaf(h0.z, __ldg(aH+3),  accH);
            accH = fmaf(h0.w, __ldg(aH+4),  accH);
            accH = fmaf(h1.x, __ldg(aH+5),  accH);
            accH = fmaf(h1.y, __ldg(aH+6),  accH);
            accH = fmaf(h1.z, __ldg(aH+7),  accH);
            accH = fmaf(h1.w, __ldg(aH+8),  accH);
            accH = fmaf(h2.x, __ldg(aH+9),  accH);
            accH = fmaf(h2.y, __ldg(aH+10), accH);
            accH = fmaf(h2.z, __ldg(aH+11), accH);
            accH = fmaf(h2.w, __ldg(aH+12), accH);

            out[r] = sa*accL + sb*accH;
        }
    }
}

// ---------------- launch ----------------------------------------------------
extern "C" void kernel_launch(void* const* d_in, const int* in_sizes, int n_in,
                              void* d_out, int out_size)
{
    const float* XL  = (const float*)d_in[0];
    const float* XH  = (const float*)d_in[1];
    const float* lc1 = (const float*)d_in[2];
    const float* lc2 = (const float*)d_in[3];
    const float* lw  = (const float*)d_in[4];
    const float* lb  = (const float*)d_in[5];
    const float* lv  = (const float*)d_in[6];
    const float* lg  = (const float*)d_in[7];
    const float* lbe = (const float*)d_in[8];
    const float* hc1 = (const float*)d_in[9];
    const float* hc2 = (const float*)d_in[10];
    const float* hw  = (const float*)d_in[11];
    const float* hb  = (const float*)d_in[12];
    const float* hv  = (const float*)d_in[13];
    const float* hg  = (const float*)d_in[14];
    const float* hbe = (const float*)d_in[15];
    const float* alpha = (const float*)d_in[16];
    float* out = (float*)d_out;

    mega_kernel<<<NBLOCKS, 256>>>(XL, XH,
        lc1, lc2, lw, lb, lv, lg, lbe,
        hc1, hc2, hw, hb, hv, hg, hbe,
        alpha, out);
}

// round 5
// speedup vs baseline: 2.7833x; 1.2021x over previous
#include <cuda_runtime.h>
#include <math.h>

#define B_ 32
#define C_ 128
#define N_ 307
#define TL 12
#define TH 13
#define TMAX 13
#define LAYERS 4
#define BN_EPS 1e-5f
#define E4 921            // float4 per (b,c) row  (307*12/4)
#define EF 3684           // floats per (b,c) row
#define NBLOCKS 512
#define NCHAIN 64
#define PADC 132

// ---------------- scratch (static __device__, no allocations) ----------------
__device__ float g_Gpart[8*2*4*B_*EF];           // (cb,ch,layer,b,e) 30.2 MB
__device__ float g_H [2*4*B_*TMAX*C_];           // (ch,layer,b,sl,c)
__device__ float g_GWpart[2*2*4*B_*TMAX*C_];     // (half,ch,layer,b,sl,c)
__device__ float g_logits[2][2*B_*TMAX*TMAX];    // double buffered per layer parity
__device__ float g_avec[2*B_*TMAX];              // final A column per (ch,b)
__device__ unsigned g_barA_count, g_barA_gen;    // all-512 barrier
__device__ unsigned g_bar64_count, g_bar64_gen;  // chain-block barrier
__device__ unsigned g_done_gen;                  // chain-done generation flag

__device__ __forceinline__ int GPidx(int cb,int ch,int i,int b){
    return (((cb*2+ch)*4+i)*B_+b)*EF;
}
__device__ __forceinline__ int Hidx(int ch,int i,int b,int s,int c){
    return (((ch*4+i)*B_+b)*TMAX+s)*C_+c;
}
__device__ __forceinline__ int GWPidx(int half,int ch,int i,int b){
    return (((half*2+ch)*4+i)*B_+b)*TMAX*C_;
}

__device__ __forceinline__ void barrier_n(unsigned* cnt, unsigned* gen, unsigned n, bool sleep){
    __threadfence();
    __syncthreads();
    if (threadIdx.x == 0){
        volatile unsigned* genp = (volatile unsigned*)gen;
        unsigned g = *genp;
        if (atomicAdd(cnt, 1u) == n - 1u){
            atomicExch(cnt, 0u);
            __threadfence();
            *genp = g + 1u;
        } else {
            if (sleep){ while (*genp == g) __nanosleep(32); }
            else      { while (*genp == g) {} }
        }
    }
    __syncthreads();
}

struct SMa { float ss[16][396]; float4 sc2[N_]; float4 sc1h[16]; };
struct SMb { float sg[1856]; float red[1536]; };
struct SMc { float A[TMAX*TMAX], A2[TMAX*TMAX];
             float GWs[TMAX*PADC], Hs[TMAX*PADC], f1w[TMAX*PADC], f2s[TMAX*PADC];
             float sS[TMAX*TMAX], slog[TMAX*TMAX], mu[TMAX], isd[TMAX]; };
struct SMd { float av[2*B_*TMAX]; };
union SMU { SMa a; SMb b; SMc c; SMd d; };

// ---- phase A chunk, compile-time NN (32 main / 19 tail) ---------------------
template<int NN>
__device__ __forceinline__ void chunkA(
    SMU& sm, const float4* __restrict__ X4, size_t xbase, int nk,
    int tid, int cl, int s12, bool act,
    float& h0, float& h1, float& h2, float& h3,
    float* __restrict__ g0p, float* __restrict__ g1p,
    float* __restrict__ g2p, float* __restrict__ g3p)
{
    __syncthreads();
    #pragma unroll
    for (int j0 = 0; j0 < 1536; j0 += 256){
        int j = j0 + tid;
        int c = j / 96, r = j - c*96;        // compile-time divisor
        if (r < NN*3)
            *(float4*)&sm.a.ss[c][r*4] = X4[xbase + (size_t)c*E4 + nk*96 + r];
    }
    __syncthreads();
    if (act){
        const float4* s2 = &sm.a.sc2[nk*32];
        #pragma unroll
        for (int nl = 0; nl < NN; nl++){
            float  v = sm.a.ss[cl][nl*12 + s12];
            float4 w = s2[nl];
            h0 = fmaf(w.x, v, h0);
            h1 = fmaf(w.y, v, h1);
            h2 = fmaf(w.z, v, h2);
            h3 = fmaf(w.w, v, h3);
        }
    }
    #pragma unroll
    for (int j0 = 0; j0 < NN*12; j0 += 256){
        int j = j0 + tid;
        if (j < NN*12){
            int nl = j / 12, sg_ = j - nl*12;
            float p0=0.f, p1=0.f, p2=0.f, p3=0.f;
            #pragma unroll
            for (int cc = 0; cc < 16; cc++){
                float  v = sm.a.ss[cc][nl*12 + sg_];
                float4 w = sm.a.sc1h[cc];
                p0 = fmaf(w.x, v, p0);
                p1 = fmaf(w.y, v, p1);
                p2 = fmaf(w.z, v, p2);
                p3 = fmaf(w.w, v, p3);
            }
            int e = nk*384 + j;
            g0p[e] = p0; g1p[e] = p1; g2p[e] = p2; g3p[e] = p3;
        }
    }
}

__global__ void __launch_bounds__(256, 4) mega_kernel(
    const float* __restrict__ XL,  const float* __restrict__ XH,
    const float* __restrict__ c1L, const float* __restrict__ c2L,
    const float* __restrict__ wL,  const float* __restrict__ bL,
    const float* __restrict__ vL,  const float* __restrict__ gL,
    const float* __restrict__ beL,
    const float* __restrict__ c1H, const float* __restrict__ c2H,
    const float* __restrict__ wH,  const float* __restrict__ bH,
    const float* __restrict__ vH,  const float* __restrict__ gH,
    const float* __restrict__ beH,
    const float* __restrict__ alpha, float* __restrict__ out)
{
    __shared__ SMU sm;
    __shared__ unsigned s_dt;
    int bid = blockIdx.x, tid = threadIdx.x;

    if (tid == 0) s_dt = *(volatile unsigned*)&g_done_gen + 1u;   // replay-safe target

    // ================= Phase A: stream X once; H (complete) + G partials ====
    {
        int group = bid >> 3, cb = bid & 7;
        int b = group >> 1, ch = group & 1;
        int cbase = cb * 16;
        const float4* X4 = (const float4*)(ch ? XH : XL);
        const float* c1 = ch ? c1H : c1L;
        const float* c2 = ch ? c2H : c2L;

        for (int t = tid; t < N_; t += 256)
            sm.a.sc2[t] = make_float4(c2[t], c2[N_+t], c2[2*N_+t], c2[3*N_+t]);
        if (tid < 16){
            int c = cbase + tid;
            sm.a.sc1h[tid] = make_float4(c1[c], c1[C_+c], c1[2*C_+c], c1[3*C_+c]);
        }

        int cl = tid / 12, s12 = tid - cl*12;
        bool act = (tid < 192);
        float h0=0.f, h1=0.f, h2=0.f, h3=0.f;

        size_t xbase = (size_t)(b*C_ + cbase) * E4;
        float* g0p = g_Gpart + GPidx(cb,ch,0,b);
        float* g1p = g_Gpart + GPidx(cb,ch,1,b);
        float* g2p = g_Gpart + GPidx(cb,ch,2,b);
        float* g3p = g_Gpart + GPidx(cb,ch,3,b);

        for (int nk = 0; nk < 9; nk++)
            chunkA<32>(sm, X4, xbase, nk, tid, cl, s12, act, h0,h1,h2,h3, g0p,g1p,g2p,g3p);
        chunkA<19>(sm, X4, xbase, 9, tid, cl, s12, act, h0,h1,h2,h3, g0p,g1p,g2p,g3p);

        if (act){
            int c = cbase + cl, sl = s12 + ch;    // logical s (high shifted)
            g_H[Hidx(ch,0,b,sl,c)] = h0;
            g_H[Hidx(ch,1,b,sl,c)] = h1;
            g_H[Hidx(ch,2,b,sl,c)] = h2;
            g_H[Hidx(ch,3,b,sl,c)] = h3;
        }
        if (ch && tid < 16){
            #pragma unroll
            for (int i = 0; i < 4; i++)
                g_H[Hidx(1,i,b,0,cbase + tid)] = 0.f;  // left-pad row
        }
    }
    barrier_n(&g_barA_count, &g_barA_gen, NBLOCKS, true);

    // ================= Phase B: GW_i[b,s,c] = sum_n G_i[b,s,n] * w_i[n,c] ===
    {
        int half = bid & 1;
        int b  = (bid >> 1) & 31;
        int i  = (bid >> 6) & 3;
        int ch =  bid >> 8;
        int nstart = half ? 154 : 0;
        int ncnt   = half ? 153 : 154;
        int e0 = nstart*12, ecnt = ncnt*12;

        for (int j = tid; j < ecnt; j += 256){
            float v = 0.f;
            #pragma unroll
            for (int cb = 0; cb < 8; cb++)
                v += g_Gpart[GPidx(cb,ch,i,b) + e0 + j];
            sm.b.sg[j] = v;
        }
        __syncthreads();

        int c  = tid & 127;
        int nh = tid >> 7;
        const float* w = (ch ? wH : wL) + (size_t)i*N_*C_;
        float acc[12];
        #pragma unroll
        for (int s = 0; s < 12; s++) acc[s] = 0.f;
        int nmid = ncnt >> 1;
        int nA = nh ? nmid : 0;
        int nB = nh ? ncnt : nmid;
        for (int nl = nA; nl < nB; nl++){
            float wv = __ldg(w + (size_t)(nstart + nl)*C_ + c);
            #pragma unroll
            for (int s = 0; s < 12; s++)
                acc[s] = fmaf(sm.b.sg[nl*12 + s], wv, acc[s]);
        }
        if (nh){
            #pragma unroll
            for (int s = 0; s < 12; s++) sm.b.red[s*128 + c] = acc[s];
        }
        __syncthreads();
        if (!nh){
            int base = GWPidx(half,ch,i,b);
            #pragma unroll
            for (int s = 0; s < 12; s++){
                float v = acc[s] + sm.b.red[s*128 + c];
                g_GWpart[base + (s + ch)*C_ + c] = v;
            }
            if (ch) g_GWpart[base + c] = 0.f;     // logical s=0 pad row
        }
    }
    barrier_n(&g_barA_count, &g_barA_gen, NBLOCKS, true);

    // ================= Phase C: 4-layer chain (64 blocks); others wait flag =
    if (bid < NCHAIN){
        int ch = bid & 1, b = bid >> 1;
        int T  = ch ? TH : TL;
        const float* bias = ch ? bH  : bL;
        const float* vvp  = ch ? vH  : vL;
        const float* gam  = ch ? gH  : gL;
        const float* bet  = ch ? beH : beL;

        if (tid < T*T){
            int s = tid / T, t = tid % T;
            sm.c.A[s*TMAX + t] = (s == t) ? 1.f : 0.f;
        }
        __syncthreads();

        for (int i = 0; i < LAYERS; i++){
            int hb = Hidx(ch,i,b,0,0);
            int g0 = GWPidx(0,ch,i,b), g1 = GWPidx(1,ch,i,b);
            for (int o = tid; o < T*C_; o += 256){
                int s = o / C_, c = o - s*C_;
                sm.c.GWs[s*PADC + c] = g_GWpart[g0 + o] + g_GWpart[g1 + o];
                sm.c.Hs [s*PADC + c] = g_H[hb + o];
            }
            __syncthreads();

            // f1w[t,c] = sum_s A[s,t]*GW[s,c]; f2[q,c] = sum_s A[s,q]*H[s,c]
            for (int o = tid; o < T*C_; o += 256){
                int t = o / C_, c = o - t*C_;
                float a1 = 0.f, a2 = 0.f;
                for (int s = 0; s < T; s++){
                    float a = sm.c.A[s*TMAX + t];
                    a1 = fmaf(a, sm.c.GWs[s*PADC + c], a1);
                    a2 = fmaf(a, sm.c.Hs [s*PADC + c], a2);
                }
                sm.c.f1w[t*PADC + c] = a1;
                sm.c.f2s[t*PADC + c] = a2;
            }
            __syncthreads();

            // scores[t,q] = sigmoid(f1w . f2 + bias)
            for (int o = tid; o < T*T; o += 256){
                int t = o / T, q = o - t*T;
                float acc = bias[(i*T + t)*T + q];
                for (int c = 0; c < C_; c++)
                    acc = fmaf(sm.c.f1w[t*PADC + c], sm.c.f2s[q*PADC + c], acc);
                sm.c.sS[t*TMAX + q] = 1.f / (1.f + __expf(-acc));
            }
            __syncthreads();

            // logits[t,q] = sum_k v[t,k]*scores[k,q]
            int buf = i & 1;
            for (int o = tid; o < T*T; o += 256){
                int t = o / T, q = o - t*T;
                float acc = 0.f;
                for (int k = 0; k < T; k++)
                    acc = fmaf(vvp[(i*T + t)*T + k], sm.c.sS[k*TMAX + q], acc);
                sm.c.slog[t*TMAX + q] = acc;
                g_logits[buf][((ch*B_ + b)*TMAX + t)*TMAX + q] = acc;
            }
            barrier_n(&g_bar64_count, &g_bar64_gen, NCHAIN, false);

            // BN stats per q over (all b, t) — redundant per block
            {
                int w = tid / 32, lane = tid % 32;
                for (int q = w; q < T; q += 8){
                    float sum = 0.f, sq = 0.f;
                    for (int j = lane; j < B_*T; j += 32){
                        int bb = j / T, t = j - bb*T;
                        float val = __ldcg(&g_logits[buf][((ch*B_ + bb)*TMAX + t)*TMAX + q]);
                        sum += val; sq += val*val;
                    }
                    #pragma unroll
                    for (int off = 16; off; off >>= 1){
                        sum += __shfl_down_sync(0xffffffff, sum, off);
                        sq  += __shfl_down_sync(0xffffffff, sq,  off);
                    }
                    if (lane == 0){
                        float cnt = (float)(B_*T);
                        float m = sum / cnt;
                        float var = sq / cnt - m*m;
                        sm.c.mu[q]  = m;
                        sm.c.isd[q] = rsqrtf(var + BN_EPS);
                    }
                }
            }
            __syncthreads();

            // normalize + softmax over q
            if (tid < T){
                int t = tid;
                float z[TMAX];
                float mx = -1e30f;
                for (int q = 0; q < T; q++){
                    float val = (sm.c.slog[t*TMAX + q] - sm.c.mu[q]) * sm.c.isd[q]
                                * gam[i*T + q] + bet[i*T + q];
                    z[q] = val;
                    mx = fmaxf(mx, val);
                }
                float sum = 0.f;
                for (int q = 0; q < T; q++){ z[q] = __expf(z[q] - mx); sum += z[q]; }
                float inv = 1.f / sum;
                for (int q = 0; q < T; q++) sm.c.sS[t*TMAX + q] = z[q] * inv;
            }
            __syncthreads();

            // A_new[s,q] = sum_t A[s,t] * S[q,t]
            for (int o = tid; o < T*T; o += 256){
                int s = o / T, q = o - s*T;
                float acc = 0.f;
                for (int t = 0; t < T; t++)
                    acc = fmaf(sm.c.A[s*TMAX + t], sm.c.sS[q*TMAX + t], acc);
                sm.c.A2[s*TMAX + q] = acc;
            }
            __syncthreads();
            for (int o = tid; o < T*T; o += 256)
                sm.c.A[(o/T)*TMAX + (o%T)] = sm.c.A2[(o/T)*TMAX + (o%T)];
            __syncthreads();
        }
        if (tid < T)
            g_avec[(ch*B_ + b)*TMAX + tid] = sm.c.A[tid*TMAX + (T-1)];

        barrier_n(&g_bar64_count, &g_bar64_gen, NCHAIN, false);
        if (bid == 0 && tid == 0){
            __threadfence();
            *(volatile unsigned*)&g_done_gen = s_dt;
        }
    } else {
        // idle blocks: wait for chain completion flag
        __syncthreads();
        if (tid == 0){
            volatile unsigned* dg = (volatile unsigned*)&g_done_gen;
            unsigned tgt = s_dt;
            while (*dg != tgt) __nanosleep(64);
            __threadfence();
        }
        __syncthreads();
    }

    // ================= Phase D: residual + alpha mix, streaming, all blocks =
    {
        for (int o = tid; o < 2*B_*TMAX; o += 256) sm.d.av[o] = g_avec[o];
        __syncthreads();

        float sa = 1.f / (1.f + expf(-alpha[0]));
        float sb = 1.f - sa;
        const int total = B_*C_*N_;
        for (int r = bid*256 + tid; r < total; r += NBLOCKS*256){
            int b = r / (C_*N_);
            const float4* xl4 = (const float4*)(XL + (size_t)r*TL);
            const float4* xh4 = (const float4*)(XH + (size_t)r*TL);
            float4 l0 = xl4[0], l1 = xl4[1], l2 = xl4[2];
            float4 h0 = xh4[0], h1 = xh4[1], h2 = xh4[2];
            const float* aL = &sm.d.av[b*TMAX];
            const float* aH = &sm.d.av[(B_ + b)*TMAX];

            float accL = l2.w;
            accL = fmaf(l0.x, aL[0],  accL);
            accL = fmaf(l0.y, aL[1],  accL);
            accL = fmaf(l0.z, aL[2],  accL);
            accL = fmaf(l0.w, aL[3],  accL);
            accL = fmaf(l1.x, aL[4],  accL);
            accL = fmaf(l1.y, aL[5],  accL);
            accL = fmaf(l1.z, aL[6],  accL);
            accL = fmaf(l1.w, aL[7],  accL);
            accL = fmaf(l2.x, aL[8],  accL);
            accL = fmaf(l2.y, aL[9],  accL);
            accL = fmaf(l2.z, aL[10], accL);
            accL = fmaf(l2.w, aL[11], accL);

            float accH = h2.w;
            accH = fmaf(h0.x, aH[1],  accH);
            accH = fmaf(h0.y, aH[2],  accH);
            accH = fmaf(h0.z, aH[3],  accH);
            accH = fmaf(h0.w, aH[4],  accH);
            accH = fmaf(h1.x, aH[5],  accH);
            accH = fmaf(h1.y, aH[6],  accH);
            accH = fmaf(h1.z, aH[7],  accH);
            accH = fmaf(h1.w, aH[8],  accH);
            accH = fmaf(h2.x, aH[9],  accH);
            accH = fmaf(h2.y, aH[10], accH);
            accH = fmaf(h2.z, aH[11], accH);
            accH = fmaf(h2.w, aH[12], accH);

            out[r] = sa*accL + sb*accH;
        }
    }
}

// ---------------- launch ----------------------------------------------------
extern "C" void kernel_launch(void* const* d_in, const int* in_sizes, int n_in,
                              void* d_out, int out_size)
{
    const float* XL  = (const float*)d_in[0];
    const float* XH  = (const float*)d_in[1];
    const float* lc1 = (const float*)d_in[2];
    const float* lc2 = (const float*)d_in[3];
    const float* lw  = (const float*)d_in[4];
    const float* lb  = (const float*)d_in[5];
    const float* lv  = (const float*)d_in[6];
    const float* lg  = (const float*)d_in[7];
    const float* lbe = (const float*)d_in[8];
    const float* hc1 = (const float*)d_in[9];
    const float* hc2 = (const float*)d_in[10];
    const float* hw  = (const float*)d_in[11];
    const float* hb  = (const float*)d_in[12];
    const float* hv  = (const float*)d_in[13];
    const float* hg  = (const float*)d_in[14];
    const float* hbe = (const float*)d_in[15];
    const float* alpha = (const float*)d_in[16];
    float* out = (float*)d_out;

    mega_kernel<<<NBLOCKS, 256>>>(XL, XH,
        lc1, lc2, lw, lb, lv, lg, lbe,
        hc1, hc2, hw, hb, hv, hg, hbe,
        alpha, out);
}